// round 17
// baseline (speedup 1.0000x reference)
#include <cuda_runtime.h>
#include <cuda_fp16.h>

// Problem constants
#define NN     512
#define NE     5
#define NL     12
#define MB     8192                 // 16 channels * 512 rows
#define NVOXP  (1u << 22)           // elements per xp slab
#define NPX    (1u << 22)           // pixels per stacked plane (512 x 8192)
#define SCALE  1.953125e-5f         // SAMPLE_SIZE_CM / N = 0.01/512
#define KFAC   170.0f               // PROBE_CTS * FL_RATIO * SA_ADJ * SA_THETA

// Packed texture backing stores (static device globals; no allocation)
__device__ __align__(16) uint2  g_pack4[NPX];    // half4: e0,e1,e2,e3  (32 MB)
__device__ __align__(16) __half g_pack1[NPX];    // e4                  (8 MB)

// ───────────────────────── pre-pass: fp32 slabs -> half4 + half planes ──────
__global__ __launch_bounds__(256) void ppm_pack_kernel(
    const float* __restrict__ xp)
{
    const unsigned i4 = (blockIdx.x << 8) + threadIdx.x;   // quad index
    const unsigned i  = i4 << 2;                            // pixel index
    if (i >= NPX) return;

    const float4 v0 = *(const float4*)(xp + i);
    const float4 v1 = *(const float4*)(xp + (1u << 22) + i);
    const float4 v2 = *(const float4*)(xp + (2u << 22) + i);
    const float4 v3 = *(const float4*)(xp + (3u << 22) + i);
    const float4 v4 = *(const float4*)(xp + ((size_t)4 << 22) + i);
    const float* f0 = (const float*)&v0;
    const float* f1 = (const float*)&v1;
    const float* f2 = (const float*)&v2;
    const float* f3 = (const float*)&v3;

    uint2 outq[4];
#pragma unroll
    for (int k = 0; k < 4; k++) {
        __half2 p01 = __floats2half2_rn(f0[k], f1[k]);
        __half2 p23 = __floats2half2_rn(f2[k], f3[k]);
        outq[k].x = *(unsigned int*)&p01;
        outq[k].y = *(unsigned int*)&p23;
    }
    // 4 consecutive uint2 = 32B; write as two uint4 stores
    *(uint4*)(g_pack4 + i)     = make_uint4(outq[0].x, outq[0].y, outq[1].x, outq[1].y);
    *(uint4*)(g_pack4 + i + 2) = make_uint4(outq[2].x, outq[2].y, outq[3].x, outq[3].y);

    __half2 e01 = __floats2half2_rn(v4.x, v4.y);
    __half2 e23 = __floats2half2_rn(v4.z, v4.w);
    uint2 e;
    e.x = *(unsigned int*)&e01;
    e.y = *(unsigned int*)&e23;
    *(uint2*)(g_pack1 + i) = e;
}

// ───────── main: warp = one output row, 8 chunks; 2 tex fetches per pixel ───
__global__ __launch_bounds__(256) void ppm_row_kernel(
    cudaTextureObject_t tq,              // half4 plane (e0..e3)
    cudaTextureObject_t t4,              // half plane (e4)
    const float* __restrict__ attCS,     // (5,)
    const float* __restrict__ dfu,       // (12,)
    const float* __restrict__ theta_p,   // (1,)
    const int*   __restrict__ lidx,      // (12,)
    float* __restrict__ out)
{
    const int tid  = threadIdx.x;
    const int lane = tid & 31;
    const int warp = tid >> 5;                    // 0..7

    const int b = (blockIdx.x << 3) + warp;       // output row
    const int c = b >> 9;
    const int h = b & (NN - 1);

    float sn, cs;
    sincosf(theta_p[0], &sn, &cs);
    const float inv = 1.0f / (float)NN;

    const float a0 = __ldg(attCS + 0), a1 = __ldg(attCS + 1), a2 = __ldg(attCS + 2),
                a3 = __ldg(attCS + 3), a4 = __ldg(attCS + 4);

    // affine: ix = cs*w + BX, iy = sn*w + BY (reference math, reassociated)
    const float KA = 0.5f - 256.0f;
    const float gy = (2.0f * (float)h + 1.0f) * inv - 1.0f;
    const float BX = cs * KA - 256.0f * sn * gy + 255.5f;
    const float BY = sn * KA + 256.0f * cs * gy + 255.5f;
    const float ybase = (float)(c << 9) + 0.5f;   // channel offset in stacked plane

    float carry = 0.0f;                            // running lac prefix (row scan)
    float acc[NE] = {0.0f, 0.0f, 0.0f, 0.0f, 0.0f};

#pragma unroll
    for (int ch = 0; ch < 8; ch++) {
        const float wfl = (float)((ch << 6) + (lane << 1));

        float conc[2][NE];
        float lacv[2];
#pragma unroll
        for (int j = 0; j < 2; j++) {
            float ix = fmaf(cs, wfl, BX) + (j ? cs : 0.0f);
            float iy = fmaf(sn, wfl, BY) + (j ? sn : 0.0f);
            ix = fminf(fmaxf(ix, 0.0f), (float)(NN - 1));
            iy = fminf(fmaxf(iy, 0.0f), (float)(NN - 1));
            // HW bilinear at (u+0.5, v+0.5); iy<=511 => row 512 has weight 0,
            // so the stacked-channel plane never mixes channels.
            const float xu = ix + 0.5f;
            const float yu = ybase + iy;

            const float4 q = tex2D<float4>(tq, xu, yu);
            const float  e4v = tex2D<float>(t4, xu, yu);
            conc[j][0] = q.x;
            conc[j][1] = q.y;
            conc[j][2] = q.z;
            conc[j][3] = q.w;
            conc[j][4] = e4v;
            lacv[j] = a0 * q.x + a1 * q.y + a2 * q.z + a3 * q.w + a4 * e4v;
        }

        // warp inclusive scan of lane pair-sums within the 64-px chunk
        const float pairsum = lacv[0] + lacv[1];
        float psc = pairsum;
#pragma unroll
        for (int o = 1; o < 32; o <<= 1) {
            const float n = __shfl_up_sync(0xffffffffu, psc, o);
            if (lane >= o) psc += n;
        }
        const float excl0 = carry + (psc - pairsum);   // row-wide exclusive prefix
        const float at0 = __expf(-excl0 * SCALE);
        const float at1 = __expf(-(excl0 + lacv[0]) * SCALE);

#pragma unroll
        for (int e = 0; e < NE; e++)
            acc[e] = fmaf(at0, conc[0][e], fmaf(at1, conc[1][e], acc[e]));

        carry += __shfl_sync(0xffffffffu, psc, 31);    // add chunk total
    }

    // one warp-wide reduction per element at row end
#pragma unroll
    for (int e = 0; e < NE; e++) {
#pragma unroll
        for (int o = 16; o > 0; o >>= 1)
            acc[e] += __shfl_xor_sync(0xffffffffu, acc[e], o);
    }

    // outputs: lanes 0..7 write up to 2 values each (12 fl_sig + transmission)
#pragma unroll
    for (int rep = 0; rep < 2; rep++) {
        const int idx = lane + (rep << 3);
        if (lane < 8) {
            if (idx < NL) {
                const int e = __ldg(lidx + idx);
                float se = acc[0];
                if (e == 1) se = acc[1]; else if (e == 2) se = acc[2];
                else if (e == 3) se = acc[3]; else if (e == 4) se = acc[4];
                out[idx * MB + b] = KFAC * __ldg(dfu + idx) * se;
            } else if (idx == NL) {
                out[NL * MB + b] = carry * SCALE;       // transmission
            }
        }
    }
}

extern "C" void kernel_launch(void* const* d_in, const int* in_sizes, int n_in,
                              void* d_out, int out_size)
{
    const float* xp      = (const float*)d_in[0];
    const float* attCS   = (const float*)d_in[1];
    const float* dfu     = (const float*)d_in[2];
    const float* theta_p = (const float*)d_in[3];
    const int*   lidx    = (const int*)d_in[4];
    float* out = (float*)d_out;

    // Textures over the packed device-global planes; created once on the first
    // (uncaptured) call. No device memory is allocated anywhere.
    static cudaTextureObject_t tq = 0, t4 = 0;
    if (tq == 0) {
        void* p4 = nullptr;
        void* p1 = nullptr;
        cudaGetSymbolAddress(&p4, g_pack4);
        cudaGetSymbolAddress(&p1, g_pack1);

        cudaTextureDesc td;
        memset(&td, 0, sizeof(td));
        td.addressMode[0] = cudaAddressModeClamp;
        td.addressMode[1] = cudaAddressModeClamp;
        td.filterMode = cudaFilterModeLinear;
        td.readMode = cudaReadModeElementType;
        td.normalizedCoords = 0;

        {   // half4 plane: 512 x 8192, pitch 4096 B
            cudaResourceDesc rd;
            memset(&rd, 0, sizeof(rd));
            rd.resType = cudaResourceTypePitch2D;
            rd.res.pitch2D.devPtr = p4;
            rd.res.pitch2D.desc = cudaCreateChannelDescHalf4();
            rd.res.pitch2D.width = NN;
            rd.res.pitch2D.height = 16 * NN;
            rd.res.pitch2D.pitchInBytes = NN * 8;
            cudaCreateTextureObject(&tq, &rd, &td, nullptr);
        }
        {   // half plane: 512 x 8192, pitch 1024 B
            cudaResourceDesc rd;
            memset(&rd, 0, sizeof(rd));
            rd.resType = cudaResourceTypePitch2D;
            rd.res.pitch2D.devPtr = p1;
            rd.res.pitch2D.desc = cudaCreateChannelDescHalf();
            rd.res.pitch2D.width = NN;
            rd.res.pitch2D.height = 16 * NN;
            rd.res.pitch2D.pitchInBytes = NN * 2;
            cudaCreateTextureObject(&t4, &rd, &td, nullptr);
        }
    }

    ppm_pack_kernel<<<NPX / 4 / 256, 256>>>(xp);
    ppm_row_kernel<<<MB / 8, 256>>>(tq, t4, attCS, dfu, theta_p, lidx, out);
}